// round 16
// baseline (speedup 1.0000x reference)
#include <cuda_runtime.h>
#include <math.h>
#include <stdint.h>

#define BSZ 2
#define SEQ 2048
#define DIM 1024
#define NH  16
#define DK  64
#define BH  (BSZ*NH)   // 32
#define MTOT (BSZ*SEQ) // 4096
#define NROWS (BH*SEQ) // 65536
#define NCT  16        // col tiles of 128 per row

// Scratch (allocation-free rule: __device__ globals)
__device__ float g_q [BSZ*SEQ*DIM];
__device__ float g_k [BSZ*SEQ*DIM];
__device__ float g_v [BSZ*SEQ*DIM];
__device__ float g_bl[BSZ*SEQ*DIM];
__device__ float g_rq[BSZ*SEQ*DIM];     // tf32-rounded inputs
__device__ float g_rk[BSZ*SEQ*DIM];
__device__ float g_rv[BSZ*SEQ*DIM];
__device__ float g_w [4*DIM*DIM];       // tf32-rounded weights
__device__ float g_smax[NROWS*NCT];
__device__ float g_ssum[NROWS*NCT];

// ---------------------------------------------------------------------------
// helpers
// ---------------------------------------------------------------------------
__device__ __forceinline__ unsigned f2tf(float x) {
    unsigned r;
    asm("cvt.rna.tf32.f32 %0, %1;" : "=r"(r) : "f"(x));
    return r;
}

__device__ __forceinline__ void mma_tf32(float c[4],
    unsigned a0, unsigned a1, unsigned a2, unsigned a3,
    unsigned b0, unsigned b1)
{
    asm volatile(
        "mma.sync.aligned.m16n8k8.row.col.f32.tf32.tf32.f32 "
        "{%0,%1,%2,%3}, {%4,%5,%6,%7}, {%8,%9}, {%0,%1,%2,%3};\n"
        : "+f"(c[0]), "+f"(c[1]), "+f"(c[2]), "+f"(c[3])
        : "r"(a0), "r"(a1), "r"(a2), "r"(a3), "r"(b0), "r"(b1));
}

__device__ __forceinline__ unsigned smem_u32(const void* p) {
    unsigned a;
    asm("{ .reg .u64 t; cvta.to.shared.u64 t, %1; cvt.u32.u64 %0, t; }"
        : "=r"(a) : "l"(p));
    return a;
}

#define CPA_COMMIT() asm volatile("cp.async.commit_group;" ::: "memory")
#define CPA_WAIT1()  asm volatile("cp.async.wait_group 1;" ::: "memory")
#define CPA_WAIT0()  asm volatile("cp.async.wait_group 0;" ::: "memory")

__device__ __forceinline__ void cpa16(const void* smem_dst, const float* gsrc) {
    unsigned sa = smem_u32(smem_dst);
    asm volatile("cp.async.cg.shared.global [%0], [%1], 16;"
                 :: "r"(sa), "l"(gsrc) : "memory");
}

// ---------------------------------------------------------------------------
// pre-round kernels
// ---------------------------------------------------------------------------
__global__ __launch_bounds__(256) void round3(
    const float* __restrict__ a, const float* __restrict__ b,
    const float* __restrict__ c,
    float* __restrict__ da, float* __restrict__ db, float* __restrict__ dc)
{
    const float* s; float* d;
    if      (blockIdx.y == 0) { s = a; d = da; }
    else if (blockIdx.y == 1) { s = b; d = db; }
    else                      { s = c; d = dc; }
    int i = blockIdx.x * 256 + threadIdx.x;
    float4 v = ((const float4*)s)[i];
    uint4 o = make_uint4(f2tf(v.x), f2tf(v.y), f2tf(v.z), f2tf(v.w));
    ((uint4*)d)[i] = o;
}

__global__ __launch_bounds__(256) void round4(
    const float* __restrict__ a, const float* __restrict__ b,
    const float* __restrict__ c, const float* __restrict__ d,
    float* __restrict__ dst)
{
    const float* s;
    if      (blockIdx.y == 0) s = a;
    else if (blockIdx.y == 1) s = b;
    else if (blockIdx.y == 2) s = c;
    else                      s = d;
    int i = blockIdx.x * 256 + threadIdx.x;
    float4 v = ((const float4*)s)[i];
    uint4 o = make_uint4(f2tf(v.x), f2tf(v.y), f2tf(v.z), f2tf(v.w));
    ((uint4*)(dst + (size_t)blockIdx.y * DIM * DIM))[i] = o;
}

// ---------------------------------------------------------------------------
// GEMM machinery: BK=32 chunks, 3-stage cp.async ring, 1 barrier per chunk.
// ---------------------------------------------------------------------------
#define TP2 36

__device__ __forceinline__ void cpa_tile32(
    float (*dst)[TP2], const float* __restrict__ src, int lda, int tid)
{
    #pragma unroll
    for (int i = 0; i < 4; i++) {
        int id = tid + i * 256;
        int r  = id >> 3;
        int c4 = (id & 7) << 2;
        cpa16(&dst[r][c4], src + (size_t)r * lda + c4);
    }
}

__device__ __forceinline__ void tile_mma32(
    const float (*As)[TP2], const float (*Bs)[TP2],
    float acc[4][4][4], int wm, int wn, int grp, int qd)
{
    #pragma unroll
    for (int kk = 0; kk < 32; kk += 8) {
        unsigned a[4][4], b[4][2];
        #pragma unroll
        for (int mi = 0; mi < 4; mi++) {
            int m = wm * 64 + mi * 16;
            a[mi][0] = __float_as_uint(As[m + grp    ][kk + qd    ]);
            a[mi][1] = __float_as_uint(As[m + grp + 8][kk + qd    ]);
            a[mi][2] = __float_as_uint(As[m + grp    ][kk + qd + 4]);
            a[mi][3] = __float_as_uint(As[m + grp + 8][kk + qd + 4]);
        }
        #pragma unroll
        for (int ni = 0; ni < 4; ni++) {
            int n = wn * 32 + ni * 8 + grp;
            b[ni][0] = __float_as_uint(Bs[n][kk + qd    ]);
            b[ni][1] = __float_as_uint(Bs[n][kk + qd + 4]);
        }
        #pragma unroll
        for (int mi = 0; mi < 4; mi++)
            #pragma unroll
            for (int ni = 0; ni < 4; ni++)
                mma_tf32(acc[mi][ni], a[mi][0], a[mi][1], a[mi][2], a[mi][3],
                         b[ni][0], b[ni][1]);
    }
}

__device__ __forceinline__ void cpa_loop32(
    const float* __restrict__ A, int lda,
    const float* __restrict__ B, int ldb, int nk,
    float (*As)[128][TP2], float (*Bs)[128][TP2],
    float acc[4][4][4], int tid, int wm, int wn, int grp, int qd)
{
    cpa_tile32(As[0], A, lda, tid);
    cpa_tile32(Bs[0], B, ldb, tid);
    CPA_COMMIT();
    cpa_tile32(As[1], A + 32, lda, tid);
    cpa_tile32(Bs[1], B + 32, ldb, tid);
    CPA_COMMIT();

    int cur = 0;
    for (int t = 0; t < nk; t++) {
        if (t < nk - 1) CPA_WAIT1(); else CPA_WAIT0();
        __syncthreads();
        tile_mma32(As[cur], Bs[cur], acc, wm, wn, grp, qd);
        if (t + 2 < nk) {
            int nxt = cur + 2; if (nxt >= 3) nxt -= 3;
            cpa_tile32(As[nxt], A + (t + 2) * 32, lda, tid);
            cpa_tile32(Bs[nxt], B + (t + 2) * 32, ldb, tid);
            CPA_COMMIT();
        }
        if (++cur == 3) cur = 0;
    }
}

#define GEMM_SMEM (3 * 128 * TP2 * 4 * 2)   // 110592 bytes

// GEMM body parameterized on tile indices (tm: M tile, tn: N tile)
__device__ __forceinline__ void gemm_body(
    const float* __restrict__ A, const float* __restrict__ W,
    const float* __restrict__ bias, float* __restrict__ C,
    int M, int N, int K, int round_out, float* sm, int tm, int tn)
{
    float (*As)[128][TP2] = (float (*)[128][TP2])sm;
    float (*Bs)[128][TP2] = (float (*)[128][TP2])(sm + 3 * 128 * TP2);

    int tid = threadIdx.x;
    int warp = tid >> 5, lane = tid & 31;
    int wm = warp >> 2, wn = warp & 3;
    int grp = lane >> 2, qd = lane & 3;

    const float* Ab = A + (size_t)(tm * 128) * K;
    const float* Wb = W + (size_t)(tn * 128) * K;
    float acc[4][4][4] = {};
    cpa_loop32(Ab, K, Wb, K, K / 32, As, Bs, acc, tid, wm, wn, grp, qd);

    int row0 = tm * 128 + wm * 64;
    int col0 = tn * 128 + wn * 32;
    #pragma unroll
    for (int mi = 0; mi < 4; mi++) {
        #pragma unroll
        for (int ni = 0; ni < 4; ni++) {
            int r  = row0 + mi * 16 + grp;
            int cc = col0 + ni * 8 + qd * 2;
            float b0 = bias[cc], b1 = bias[cc + 1];
            float v00 = acc[mi][ni][0] + b0, v01 = acc[mi][ni][1] + b1;
            float v10 = acc[mi][ni][2] + b0, v11 = acc[mi][ni][3] + b1;
            if (round_out) {
                v00 = __uint_as_float(f2tf(v00)); v01 = __uint_as_float(f2tf(v01));
                v10 = __uint_as_float(f2tf(v10)); v11 = __uint_as_float(f2tf(v11));
            }
            *(float2*)(C + (size_t)r * N + cc)       = make_float2(v00, v01);
            *(float2*)(C + (size_t)(r + 8) * N + cc) = make_float2(v10, v11);
        }
    }
}

// Q,K projections only: grid (8, 32, 2)
__global__ __launch_bounds__(256, 2) void gemm_qk(
    const float* __restrict__ rq, const float* __restrict__ rk,
    const float* __restrict__ w,
    const float* __restrict__ bq, const float* __restrict__ bk,
    float* __restrict__ oq, float* __restrict__ ok)
{
    extern __shared__ float sm[];
    int z = blockIdx.z;
    const float* A   = z ? rk : rq;
    const float* bias= z ? bk : bq;
    float* C         = z ? ok : oq;
    gemm_body(A, w + (size_t)z * DIM * DIM, bias, C, MTOT, DIM, DIM, 1, sm,
              blockIdx.y, blockIdx.x);
}

// out projection: grid (8, 32)
__global__ __launch_bounds__(256, 2) void gemm_cpa(
    const float* __restrict__ A, const float* __restrict__ W,
    const float* __restrict__ bias, float* __restrict__ C,
    int M, int N, int K, int round_out)
{
    extern __shared__ float sm[];
    gemm_body(A, W, bias, C, M, N, K, round_out, sm, blockIdx.y, blockIdx.x);
}

// ---------------------------------------------------------------------------
// Merged scores + V-projection launch. grid (16, 16, 33):
//   z == 0 : 256 blocks -> V GEMM tiles (tm = id>>3 in 0..31, tn = id&7 in 0..7)
//   z >= 1 : scores for bh = z-1
// ---------------------------------------------------------------------------
#define QPAD 68
#define SVG_SMEM GEMM_SMEM   // max(gemm 110592, scores 69632)

__global__ __launch_bounds__(256, 2) void attn_scores_vg(
    float* __restrict__ score,
    const float* __restrict__ rv, const float* __restrict__ w,
    const float* __restrict__ bv)
{
    extern __shared__ float sm[];

    if (blockIdx.z == 0) {
        int id = blockIdx.y * 16 + blockIdx.x;   // 0..255
        gemm_body(rv, w + 2 * (size_t)DIM * DIM, bv, g_v,
                  MTOT, DIM, DIM, 1, sm, id >> 3, id & 7);
        return;
    }

    float (*Qs)[QPAD] = (float (*)[QPAD])sm;
    float (*Ks)[QPAD] = (float (*)[QPAD])(sm + 128 * QPAD);
    float (*rstat)[4] = (float (*)[4])sm;   // reuse after mainloop

    int tid = threadIdx.x;
    int warp = tid >> 5, lane = tid & 31;
    int wm = warp >> 2, wn = warp & 3;
    int grp = lane >> 2, qd = lane & 3;
    int bh = blockIdx.z - 1, b = bh >> 4, h = bh & 15;

    const float* qb = g_q + (size_t)b * SEQ * DIM + (size_t)(blockIdx.y * 128) * DIM + h * DK;
    const float* kb = g_k + (size_t)b * SEQ * DIM + (size_t)(blockIdx.x * 128) * DIM + h * DK;

    #pragma unroll
    for (int i = 0; i < 8; i++) {
        int id = tid + i * 256;
        int r  = id >> 4;
        int c4 = (id & 15) << 2;
        cpa16(&Qs[r][c4], qb + (size_t)r * DIM + c4);
    }
    #pragma unroll
    for (int i = 0; i < 8; i++) {
        int id = tid + i * 256;
        int r  = id >> 4;
        int c4 = (id & 15) << 2;
        cpa16(&Ks[r][c4], kb + (size_t)r * DIM + c4);
    }
    CPA_COMMIT();
    CPA_WAIT0();
    __syncthreads();

    float acc[4][4][4] = {};
    #pragma unroll
    for (int kk8 = 0; kk8 < 64; kk8 += 8) {
        unsigned a[4][4], bf[4][2];
        #pragma unroll
        for (int mi = 0; mi < 4; mi++) {
            int m = wm * 64 + mi * 16;
            a[mi][0] = __float_as_uint(Qs[m + grp    ][kk8 + qd    ]);
            a[mi][1] = __float_as_uint(Qs[m + grp + 8][kk8 + qd    ]);
            a[mi][2] = __float_as_uint(Qs[m + grp    ][kk8 + qd + 4]);
            a[mi][3] = __float_as_uint(Qs[m + grp + 8][kk8 + qd + 4]);
        }
        #pragma unroll
        for (int ni = 0; ni < 4; ni++) {
            int n = wn * 32 + ni * 8 + grp;
            bf[ni][0] = __float_as_uint(Ks[n][kk8 + qd    ]);
            bf[ni][1] = __float_as_uint(Ks[n][kk8 + qd + 4]);
        }
        #pragma unroll
        for (int mi = 0; mi < 4; mi++)
            #pragma unroll
            for (int ni = 0; ni < 4; ni++)
                mma_tf32(acc[mi][ni], a[mi][0], a[mi][1], a[mi][2], a[mi][3],
                         bf[ni][0], bf[ni][1]);
    }
    __syncthreads();

    const float alpha = 0.125f;
    #pragma unroll
    for (int mi = 0; mi < 4; mi++)
        #pragma unroll
        for (int ni = 0; ni < 4; ni++)
            #pragma unroll
            for (int j = 0; j < 4; j++)
                acc[mi][ni][j] *= alpha;

    float msel[4][2];
    #pragma unroll
    for (int mi = 0; mi < 4; mi++) {
        float mA = -1e30f, mB = -1e30f;
        #pragma unroll
        for (int ni = 0; ni < 4; ni++) {
            mA = fmaxf(mA, fmaxf(acc[mi][ni][0], acc[mi][ni][1]));
            mB = fmaxf(mB, fmaxf(acc[mi][ni][2], acc[mi][ni][3]));
        }
        mA = fmaxf(mA, __shfl_xor_sync(0xffffffffu, mA, 1));
        mA = fmaxf(mA, __shfl_xor_sync(0xffffffffu, mA, 2));
        mB = fmaxf(mB, __shfl_xor_sync(0xffffffffu, mB, 1));
        mB = fmaxf(mB, __shfl_xor_sync(0xffffffffu, mB, 2));
        int rA = wm * 64 + mi * 16 + grp;
        if (qd == 0) { rstat[rA][wn] = mA; rstat[rA + 8][wn] = mB; }
    }
    __syncthreads();
    #pragma unroll
    for (int mi = 0; mi < 4; mi++) {
        int rA = wm * 64 + mi * 16 + grp;
        msel[mi][0] = fmaxf(fmaxf(rstat[rA][0],     rstat[rA][1]),
                            fmaxf(rstat[rA][2],     rstat[rA][3]));
        msel[mi][1] = fmaxf(fmaxf(rstat[rA + 8][0], rstat[rA + 8][1]),
                            fmaxf(rstat[rA + 8][2], rstat[rA + 8][3]));
    }
    __syncthreads();

    float ssel[4][2];
    #pragma unroll
    for (int mi = 0; mi < 4; mi++) {
        float sA = 0.f, sB = 0.f;
        #pragma unroll
        for (int ni = 0; ni < 4; ni++) {
            acc[mi][ni][0] = __expf(acc[mi][ni][0] - msel[mi][0]);
            acc[mi][ni][1] = __expf(acc[mi][ni][1] - msel[mi][0]);
            acc[mi][ni][2] = __expf(acc[mi][ni][2] - msel[mi][1]);
            acc[mi][ni][3] = __expf(acc[mi][ni][3] - msel[mi][1]);
            sA += acc[mi][ni][0] + acc[mi][ni][1];
            sB += acc[mi][ni][2] + acc[mi][ni][3];
        }
        sA += __shfl_xor_sync(0xffffffffu, sA, 1);
        sA += __shfl_xor_sync(0xffffffffu, sA, 2);
        sB += __shfl_xor_sync(0xffffffffu, sB, 1);
        sB += __shfl_xor_sync(0xffffffffu, sB, 2);
        int rA = wm * 64 + mi * 16 + grp;
        if (qd == 0) { rstat[rA][wn] = sA; rstat[rA + 8][wn] = sB; }
    }
    __syncthreads();
    #pragma unroll
    for (int mi = 0; mi < 4; mi++) {
        int rA = wm * 64 + mi * 16 + grp;
        ssel[mi][0] = (rstat[rA][0]     + rstat[rA][1])
                    + (rstat[rA][2]     + rstat[rA][3]);
        ssel[mi][1] = (rstat[rA + 8][0] + rstat[rA + 8][1])
                    + (rstat[rA + 8][2] + rstat[rA + 8][3]);
    }

    float* ob = score + (size_t)bh * SEQ * SEQ;
    int row0 = blockIdx.y * 128 + wm * 64;
    int col0 = blockIdx.x * 128 + wn * 32;
    #pragma unroll
    for (int mi = 0; mi < 4; mi++) {
        #pragma unroll
        for (int ni = 0; ni < 4; ni++) {
            int r  = row0 + mi * 16 + grp;
            int cc = col0 + ni * 8 + qd * 2;
            *(float2*)(ob + (size_t)r * SEQ + cc) =
                make_float2(acc[mi][ni][0], acc[mi][ni][1]);
            *(float2*)(ob + (size_t)(r + 8) * SEQ + cc) =
                make_float2(acc[mi][ni][2], acc[mi][ni][3]);
        }
    }

    if (wn == 0 && qd == 0) {
        #pragma unroll
        for (int mi = 0; mi < 4; mi++) {
            #pragma unroll
            for (int half = 0; half < 2; half++) {
                int rowg = blockIdx.y * 128 + wm * 64 + mi * 16 + half * 8 + grp;
                size_t idx = ((size_t)(bh << 11) + rowg) * NCT + blockIdx.x;
                g_smax[idx] = msel[mi][half];
                g_ssum[idx] = ssel[mi][half];
            }
        }
    }
}

// ---------------------------------------------------------------------------
// PV v3: inline combine (per-block factor table) + 256 threads, CHK=32.
// ---------------------------------------------------------------------------
#define CHK2 32
#define PVP 36
#define PV_SMEM ((128 * PVP + 2 * CHK2 * 72) * 4)   // 36864 bytes dynamic

__global__ __launch_bounds__(256, 2) void attn_pv3(float* __restrict__ score)
{
    extern __shared__ float smraw[];
    unsigned (*Ps)[PVP]       = (unsigned (*)[PVP])smraw;
    unsigned (*Vs)[CHK2][72]  = (unsigned (*)[CHK2][72])(smraw + 128 * PVP);
    __shared__ float fb_s[128][NCT];

    int tid = threadIdx.x;
    int warp = tid >> 5, lane = tid & 31;
    int wm = warp >> 2, wn = warp & 3;     // 2 x 4
    int grp = lane >> 2, qd = lane & 3;
    int bh = blockIdx.y, b = bh >> 4, h = bh & 15;
    int row0 = blockIdx.x * 128;

    float* pb = score + (size_t)bh * SEQ * SEQ + (size_t)row0 * SEQ;
    const float* vb = g_v + (size_t)b * SEQ * DIM + h * DK;

    // inline combine: one thread per row computes the 16 tile factors
    if (tid < 128) {
        size_t row_g = (size_t)(bh << 11) + row0 + tid;
        const float* mx = g_smax + row_g * NCT;
        const float* sv = g_ssum + row_g * NCT;
        float mv[NCT];
        float m = -1e30f;
        #pragma unroll
        for (int i = 0; i < NCT; i++) { mv[i] = mx[i]; m = fmaxf(m, mv[i]); }
        float s = 0.f;
        float ev[NCT];
        #pragma unroll
        for (int i = 0; i < NCT; i++) { ev[i] = __expf(mv[i] - m); s += sv[i] * ev[i]; }
        float inv = 1.0f / s;
        #pragma unroll
        for (int i = 0; i < NCT; i++) fb_s[tid][i] = ev[i] * inv;
    }
    __syncthreads();

    float acc[4][2][4] = {};
    float4 pe[4]; float pf[4]; float4 pvv[2];

    // prologue: chunk 0
    #pragma unroll
    for (int i = 0; i < 4; i++) {
        int id = tid + i * 256;
        int r  = id >> 3;
        int c4 = (id & 7) << 2;
        pe[i] = *(const float4*)(pb + (size_t)r * SEQ + c4);
        pf[i] = fb_s[r][0];
    }
    #pragma unroll
    for (int i = 0; i < 2; i++) {
        int id = tid + i * 256;
        int r  = id >> 4;
        int c4 = (id & 15) << 2;
        pvv[i] = *(const float4*)(vb + (size_t)r * DIM + c4);
    }
    #pragma unroll
    for (int i = 0; i < 4; i++) {
        int id = tid + i * 256;
        int r  = id >> 3;
        int c4 = (id & 7) << 2;
        float4 p = make_float4(pe[i].x * pf[i], pe[i].y * pf[i],
                               pe[i].z * pf[i], pe[i].w * pf[i]);
        *(float4*)(pb + (size_t)r * SEQ + c4) = p;
        *(uint4*)&Ps[r][c4] = make_uint4(f2tf(p.x), f2tf(p.y), f2tf(p.z), f2tf(p.w));
    }
    #pragma unroll
    for (int i = 0; i < 2; i++) {
        int id = tid + i * 256;
        int r  = id >> 4;
        int c4 = (id & 15) << 2;
        *(uint4*)&Vs[0][r][c4] = make_uint4(
            __float_as_uint(pvv[i].x), __float_as_uint(pvv[i].y),
            __float_as_uint(pvv[i].z), __float_as_uint(pvv[i].w));
    }
    __syncthreads();

    const int NTCH = SEQ / CHK2;   // 64
    for (int t = 0; t < NTCH; t++) {
        int cur = t & 1;
        if (t + 1 < NTCH) {
            int ct = (t + 1) >> 2;
            #pragma unroll
            for (int i = 0; i < 4; i++) {
                int id = tid + i * 256;
                int r  = id >> 3;
                int c4 = (id & 7) << 2;
                pe[i] = *(const float4*)(pb + (size_t)r * SEQ + (t + 1) * CHK2 + c4);
                pf[i] = fb_s[r][ct];
            }
            #pragma unroll
            for (int i = 0; i < 2; i++) {
                int id = tid + i * 256;
                int r  = id >> 4;
                int c4 = (id & 15) << 2;
                pvv[i] = *(const float4*)(vb + (size_t)((t + 1) * CHK2 + r) * DIM + c4);
            }
        }

        // PV MMA: acc += P[128xCHK2] @ V[CHK2x64]; warp tile 64x16
        #pragma unroll
        for (int kk = 0; kk < CHK2; kk += 8) {
            unsigned a[4][4], bf[2][2];
            #pragma unroll
            for (int mi = 0; mi < 4; mi++) {
                int m = wm * 64 + mi * 16;
                a[mi][0] = Ps[m + grp    ][kk + qd    ];
                a[mi][1] = Ps[m + grp + 8][kk + qd    ];
                a[mi][2] = Ps[m + grp    ][kk + qd + 4];
                a[mi][3] = Ps[m + grp + 8][kk + qd + 4];
            }
            #pragma unroll
            for (int ni = 0; ni < 2; ni++) {
                int n = wn * 16 + ni * 8 + grp;
                bf[ni][0] = Vs[cur][kk + qd    ][n];
                bf[ni][1] = Vs[cur][kk + qd + 4][n];
            }
            #pragma unroll
            for (int mi = 0; mi < 4; mi++)
                #pragma unroll
                for (int ni = 0; ni < 2; ni++)
                    mma_tf32(acc[mi][ni], a[mi][0], a[mi][1], a[mi][2], a[mi][3],
                             bf[ni][0], bf[ni][1]);
        }
        __syncthreads();   // MMA reads of Ps/Vs[cur] done

        if (t + 1 < NTCH) {
            int nxt = cur ^ 1;
            #pragma unroll
            for (int i = 0; i < 4; i++) {
                int id = tid + i * 256;
                int r  = id >> 3;
                int c4 = (id & 7) << 2;
                float4 p = make_float4(pe[i].x * pf[i], pe[i].y * pf[i],
                                       pe[i].z * pf[i], pe[i].w * pf[i]);
                *(float4*)(pb + (size_t)r * SEQ + (t + 1) * CHK2 + c4) = p;
                *(uint4*)&Ps[r][c4] = make_uint4(f2tf(p.x), f2tf(p.y), f2tf(p.z), f2tf(p.w));
            }
            #pragma unroll
            for (int i = 0; i < 2; i++) {
                int id = tid + i * 256;
                int r  = id >> 4;
                int c4 = (id & 15) << 2;
                *(uint4*)&Vs[nxt][r][c4] = make_uint4(
                    __float_as_uint(pvv[i].x), __float_as_uint(pvv[i].y),
                    __float_as_uint(pvv[i].z), __float_as_uint(pvv[i].w));
            }
            __syncthreads();
        }
    }

    // store blended pre-rounded to tf32 bits for the cvt-free out-proj GEMM
    float* ob = g_bl + (size_t)b * SEQ * DIM;
    int r0 = row0 + wm * 64;
    int c0 = h * DK + wn * 16;
    #pragma unroll
    for (int mi = 0; mi < 4; mi++) {
        #pragma unroll
        for (int ni = 0; ni < 2; ni++) {
            int r  = r0 + mi * 16 + grp;
            int cc = c0 + ni * 8 + qd * 2;
            float2 o0 = make_float2(__uint_as_float(f2tf(acc[mi][ni][0])),
                                    __uint_as_float(f2tf(acc[mi][ni][1])));
            float2 o1 = make_float2(__uint_as_float(f2tf(acc[mi][ni][2])),
                                    __uint_as_float(f2tf(acc[mi][ni][3])));
            *(float2*)(ob + (size_t)r * DIM + cc)       = o0;
            *(float2*)(ob + (size_t)(r + 8) * DIM + cc) = o1;
        }
    }
}

// ---------------------------------------------------------------------------
extern "C" void kernel_launch(void* const* d_in, const int* in_sizes, int n_in,
                              void* d_out, int out_size)
{
    const float* query = (const float*)d_in[0];
    const float* key   = (const float*)d_in[1];
    const float* value = (const float*)d_in[2];
    const float* Wq    = (const float*)d_in[3];
    const float* bq    = (const float*)d_in[4];
    const float* Wk    = (const float*)d_in[5];
    const float* bk    = (const float*)d_in[6];
    const float* Wv    = (const float*)d_in[7];
    const float* bv    = (const float*)d_in[8];
    const float* Wo    = (const float*)d_in[9];
    const float* bo    = (const float*)d_in[10];

    float* out   = (float*)d_out;                          // [B,S,D]
    float* score = out + (size_t)BSZ * SEQ * DIM;          // [B,H,S,S]

    float *pq, *pk, *pbl, *prq, *prk, *prv, *pw;
    cudaGetSymbolAddress((void**)&pq,  g_q);
    cudaGetSymbolAddress((void**)&pk,  g_k);
    cudaGetSymbolAddress((void**)&pbl, g_bl);
    cudaGetSymbolAddress((void**)&prq, g_rq);
    cudaGetSymbolAddress((void**)&prk, g_rk);
    cudaGetSymbolAddress((void**)&prv, g_rv);
    cudaGetSymbolAddress((void**)&pw,  g_w);

    cudaFuncSetAttribute(gemm_qk,
        cudaFuncAttributeMaxDynamicSharedMemorySize, GEMM_SMEM);
    cudaFuncSetAttribute(gemm_cpa,
        cudaFuncAttributeMaxDynamicSharedMemorySize, GEMM_SMEM);
    cudaFuncSetAttribute(attn_scores_vg,
        cudaFuncAttributeMaxDynamicSharedMemorySize, SVG_SMEM);
    cudaFuncSetAttribute(attn_pv3,
        cudaFuncAttributeMaxDynamicSharedMemorySize, PV_SMEM);

    // pre-round inputs + weights to tf32 bits
    round3<<<dim3(MTOT * DIM / 4 / 256, 3), 256>>>(query, key, value, prq, prk, prv);
    round4<<<dim3(DIM * DIM / 4 / 256, 4), 256>>>(Wq, Wk, Wv, Wo, pw);

    // Q,K projections
    gemm_qk<<<dim3(DIM / 128, MTOT / 128, 2), 256, GEMM_SMEM>>>(
        prq, prk, pw, bq, bk, pq, pk);

    // scores (z=1..32) + V projection (z=0) in one launch
    attn_scores_vg<<<dim3(SEQ / 128, SEQ / 128, BH + 1), 256, SVG_SMEM>>>(
        score, prv, pw, bv);

    // PV with inline combine
    attn_pv3<<<dim3(SEQ / 128, BH), 256, PV_SMEM>>>(score);

    // out projection
    gemm_cpa<<<dim3(DIM / 128, MTOT / 128), 256, GEMM_SMEM>>>(
        pbl, pw + 3 * (size_t)DIM * DIM, bo, out, MTOT, DIM, DIM, 0);
}

// round 17
// speedup vs baseline: 1.4194x; 1.4194x over previous
#include <cuda_runtime.h>
#include <math.h>
#include <stdint.h>

#define BSZ 2
#define SEQ 2048
#define DIM 1024
#define NH  16
#define DK  64
#define BH  (BSZ*NH)   // 32
#define MTOT (BSZ*SEQ) // 4096
#define NROWS (BH*SEQ) // 65536
#define NCT  16        // col tiles of 128 per row

// Scratch (allocation-free rule: __device__ globals)
__device__ float g_q [BSZ*SEQ*DIM];
__device__ float g_k [BSZ*SEQ*DIM];
__device__ float g_v [BSZ*SEQ*DIM];
__device__ float g_bl[BSZ*SEQ*DIM];
__device__ float g_rq[BSZ*SEQ*DIM];     // tf32-rounded inputs
__device__ float g_rk[BSZ*SEQ*DIM];
__device__ float g_rv[BSZ*SEQ*DIM];
__device__ float g_w [4*DIM*DIM];       // tf32-rounded weights
__device__ float g_smax[NROWS*NCT];
__device__ float g_ssum[NROWS*NCT];

// ---------------------------------------------------------------------------
// helpers
// ---------------------------------------------------------------------------
__device__ __forceinline__ unsigned f2tf(float x) {
    unsigned r;
    asm("cvt.rna.tf32.f32 %0, %1;" : "=r"(r) : "f"(x));
    return r;
}

__device__ __forceinline__ void mma_tf32(float c[4],
    unsigned a0, unsigned a1, unsigned a2, unsigned a3,
    unsigned b0, unsigned b1)
{
    asm volatile(
        "mma.sync.aligned.m16n8k8.row.col.f32.tf32.tf32.f32 "
        "{%0,%1,%2,%3}, {%4,%5,%6,%7}, {%8,%9}, {%0,%1,%2,%3};\n"
        : "+f"(c[0]), "+f"(c[1]), "+f"(c[2]), "+f"(c[3])
        : "r"(a0), "r"(a1), "r"(a2), "r"(a3), "r"(b0), "r"(b1));
}

__device__ __forceinline__ unsigned smem_u32(const void* p) {
    unsigned a;
    asm("{ .reg .u64 t; cvta.to.shared.u64 t, %1; cvt.u32.u64 %0, t; }"
        : "=r"(a) : "l"(p));
    return a;
}

#define CPA_COMMIT() asm volatile("cp.async.commit_group;" ::: "memory")
#define CPA_WAIT1()  asm volatile("cp.async.wait_group 1;" ::: "memory")
#define CPA_WAIT0()  asm volatile("cp.async.wait_group 0;" ::: "memory")

__device__ __forceinline__ void cpa16(const void* smem_dst, const float* gsrc) {
    unsigned sa = smem_u32(smem_dst);
    asm volatile("cp.async.cg.shared.global [%0], [%1], 16;"
                 :: "r"(sa), "l"(gsrc) : "memory");
}

// ---------------------------------------------------------------------------
// pre-round kernels
// ---------------------------------------------------------------------------
__global__ __launch_bounds__(256) void round3(
    const float* __restrict__ a, const float* __restrict__ b,
    const float* __restrict__ c,
    float* __restrict__ da, float* __restrict__ db, float* __restrict__ dc)
{
    const float* s; float* d;
    if      (blockIdx.y == 0) { s = a; d = da; }
    else if (blockIdx.y == 1) { s = b; d = db; }
    else                      { s = c; d = dc; }
    int i = blockIdx.x * 256 + threadIdx.x;
    float4 v = ((const float4*)s)[i];
    uint4 o = make_uint4(f2tf(v.x), f2tf(v.y), f2tf(v.z), f2tf(v.w));
    ((uint4*)d)[i] = o;
}

__global__ __launch_bounds__(256) void round4(
    const float* __restrict__ a, const float* __restrict__ b,
    const float* __restrict__ c, const float* __restrict__ d,
    float* __restrict__ dst)
{
    const float* s;
    if      (blockIdx.y == 0) s = a;
    else if (blockIdx.y == 1) s = b;
    else if (blockIdx.y == 2) s = c;
    else                      s = d;
    int i = blockIdx.x * 256 + threadIdx.x;
    float4 v = ((const float4*)s)[i];
    uint4 o = make_uint4(f2tf(v.x), f2tf(v.y), f2tf(v.z), f2tf(v.w));
    ((uint4*)(dst + (size_t)blockIdx.y * DIM * DIM))[i] = o;
}

// ---------------------------------------------------------------------------
// GEMM machinery: BK=32 chunks, 3-stage cp.async ring, 1 barrier per chunk.
// ---------------------------------------------------------------------------
#define TP2 36

__device__ __forceinline__ void cpa_tile32(
    float (*dst)[TP2], const float* __restrict__ src, int lda, int tid)
{
    #pragma unroll
    for (int i = 0; i < 4; i++) {
        int id = tid + i * 256;
        int r  = id >> 3;
        int c4 = (id & 7) << 2;
        cpa16(&dst[r][c4], src + (size_t)r * lda + c4);
    }
}

__device__ __forceinline__ void tile_mma32(
    const float (*As)[TP2], const float (*Bs)[TP2],
    float acc[4][4][4], int wm, int wn, int grp, int qd)
{
    #pragma unroll
    for (int kk = 0; kk < 32; kk += 8) {
        unsigned a[4][4], b[4][2];
        #pragma unroll
        for (int mi = 0; mi < 4; mi++) {
            int m = wm * 64 + mi * 16;
            a[mi][0] = __float_as_uint(As[m + grp    ][kk + qd    ]);
            a[mi][1] = __float_as_uint(As[m + grp + 8][kk + qd    ]);
            a[mi][2] = __float_as_uint(As[m + grp    ][kk + qd + 4]);
            a[mi][3] = __float_as_uint(As[m + grp + 8][kk + qd + 4]);
        }
        #pragma unroll
        for (int ni = 0; ni < 4; ni++) {
            int n = wn * 32 + ni * 8 + grp;
            b[ni][0] = __float_as_uint(Bs[n][kk + qd    ]);
            b[ni][1] = __float_as_uint(Bs[n][kk + qd + 4]);
        }
        #pragma unroll
        for (int mi = 0; mi < 4; mi++)
            #pragma unroll
            for (int ni = 0; ni < 4; ni++)
                mma_tf32(acc[mi][ni], a[mi][0], a[mi][1], a[mi][2], a[mi][3],
                         b[ni][0], b[ni][1]);
    }
}

__device__ __forceinline__ void cpa_loop32(
    const float* __restrict__ A, int lda,
    const float* __restrict__ B, int ldb, int nk,
    float (*As)[128][TP2], float (*Bs)[128][TP2],
    float acc[4][4][4], int tid, int wm, int wn, int grp, int qd)
{
    cpa_tile32(As[0], A, lda, tid);
    cpa_tile32(Bs[0], B, ldb, tid);
    CPA_COMMIT();
    cpa_tile32(As[1], A + 32, lda, tid);
    cpa_tile32(Bs[1], B + 32, ldb, tid);
    CPA_COMMIT();

    int cur = 0;
    for (int t = 0; t < nk; t++) {
        if (t < nk - 1) CPA_WAIT1(); else CPA_WAIT0();
        __syncthreads();
        tile_mma32(As[cur], Bs[cur], acc, wm, wn, grp, qd);
        if (t + 2 < nk) {
            int nxt = cur + 2; if (nxt >= 3) nxt -= 3;
            cpa_tile32(As[nxt], A + (t + 2) * 32, lda, tid);
            cpa_tile32(Bs[nxt], B + (t + 2) * 32, ldb, tid);
            CPA_COMMIT();
        }
        if (++cur == 3) cur = 0;
    }
}

#define GEMM_SMEM (3 * 128 * TP2 * 4 * 2)   // 110592 bytes

__device__ __forceinline__ void gemm_body(
    const float* __restrict__ A, const float* __restrict__ W,
    const float* __restrict__ bias, float* __restrict__ C,
    int M, int N, int K, int round_out, float* sm, int tm, int tn)
{
    float (*As)[128][TP2] = (float (*)[128][TP2])sm;
    float (*Bs)[128][TP2] = (float (*)[128][TP2])(sm + 3 * 128 * TP2);

    int tid = threadIdx.x;
    int warp = tid >> 5, lane = tid & 31;
    int wm = warp >> 2, wn = warp & 3;
    int grp = lane >> 2, qd = lane & 3;

    const float* Ab = A + (size_t)(tm * 128) * K;
    const float* Wb = W + (size_t)(tn * 128) * K;
    float acc[4][4][4] = {};
    cpa_loop32(Ab, K, Wb, K, K / 32, As, Bs, acc, tid, wm, wn, grp, qd);

    int row0 = tm * 128 + wm * 64;
    int col0 = tn * 128 + wn * 32;
    #pragma unroll
    for (int mi = 0; mi < 4; mi++) {
        #pragma unroll
        for (int ni = 0; ni < 4; ni++) {
            int r  = row0 + mi * 16 + grp;
            int cc = col0 + ni * 8 + qd * 2;
            float b0 = bias[cc], b1 = bias[cc + 1];
            float v00 = acc[mi][ni][0] + b0, v01 = acc[mi][ni][1] + b1;
            float v10 = acc[mi][ni][2] + b0, v11 = acc[mi][ni][3] + b1;
            if (round_out) {
                v00 = __uint_as_float(f2tf(v00)); v01 = __uint_as_float(f2tf(v01));
                v10 = __uint_as_float(f2tf(v10)); v11 = __uint_as_float(f2tf(v11));
            }
            *(float2*)(C + (size_t)r * N + cc)       = make_float2(v00, v01);
            *(float2*)(C + (size_t)(r + 8) * N + cc) = make_float2(v10, v11);
        }
    }
}

// Q,K projections: grid (8, 32, 2)
__global__ __launch_bounds__(256, 2) void gemm_qk(
    const float* __restrict__ rq, const float* __restrict__ rk,
    const float* __restrict__ w,
    const float* __restrict__ bq, const float* __restrict__ bk,
    float* __restrict__ oq, float* __restrict__ ok)
{
    extern __shared__ float sm[];
    int z = blockIdx.z;
    const float* A   = z ? rk : rq;
    const float* bias= z ? bk : bq;
    float* C         = z ? ok : oq;
    gemm_body(A, w + (size_t)z * DIM * DIM, bias, C, MTOT, DIM, DIM, 1, sm,
              blockIdx.y, blockIdx.x);
}

// generic single GEMM: grid (8, 32)
__global__ __launch_bounds__(256, 2) void gemm_cpa(
    const float* __restrict__ A, const float* __restrict__ W,
    const float* __restrict__ bias, float* __restrict__ C,
    int M, int N, int K, int round_out)
{
    extern __shared__ float sm[];
    gemm_body(A, W, bias, C, M, N, K, round_out, sm, blockIdx.y, blockIdx.x);
}

// ---------------------------------------------------------------------------
// scores: Q,K tiles fully resident (K=64), inputs pre-rounded (no cvt).
// Writes e = exp(x/8 - m_tile) + per-row-tile (max,sum) partials.
// ---------------------------------------------------------------------------
#define QPAD 68
#define SC_SMEM (2 * 128 * QPAD * 4)   // 69632

__global__ __launch_bounds__(256, 2) void attn_scores_v3(float* __restrict__ score)
{
    extern __shared__ float sm[];
    float (*Qs)[QPAD] = (float (*)[QPAD])sm;
    float (*Ks)[QPAD] = (float (*)[QPAD])(sm + 128 * QPAD);
    float (*rstat)[4] = (float (*)[4])sm;   // reuse after mainloop

    int tid = threadIdx.x;
    int warp = tid >> 5, lane = tid & 31;
    int wm = warp >> 2, wn = warp & 3;
    int grp = lane >> 2, qd = lane & 3;
    int bh = blockIdx.z, b = bh >> 4, h = bh & 15;

    const float* qb = g_q + (size_t)b * SEQ * DIM + (size_t)(blockIdx.y * 128) * DIM + h * DK;
    const float* kb = g_k + (size_t)b * SEQ * DIM + (size_t)(blockIdx.x * 128) * DIM + h * DK;

    #pragma unroll
    for (int i = 0; i < 8; i++) {
        int id = tid + i * 256;
        int r  = id >> 4;
        int c4 = (id & 15) << 2;
        cpa16(&Qs[r][c4], qb + (size_t)r * DIM + c4);
    }
    #pragma unroll
    for (int i = 0; i < 8; i++) {
        int id = tid + i * 256;
        int r  = id >> 4;
        int c4 = (id & 15) << 2;
        cpa16(&Ks[r][c4], kb + (size_t)r * DIM + c4);
    }
    CPA_COMMIT();
    CPA_WAIT0();
    __syncthreads();

    float acc[4][4][4] = {};
    #pragma unroll
    for (int kk8 = 0; kk8 < 64; kk8 += 8) {
        unsigned a[4][4], bf[4][2];
        #pragma unroll
        for (int mi = 0; mi < 4; mi++) {
            int m = wm * 64 + mi * 16;
            a[mi][0] = __float_as_uint(Qs[m + grp    ][kk8 + qd    ]);
            a[mi][1] = __float_as_uint(Qs[m + grp + 8][kk8 + qd    ]);
            a[mi][2] = __float_as_uint(Qs[m + grp    ][kk8 + qd + 4]);
            a[mi][3] = __float_as_uint(Qs[m + grp + 8][kk8 + qd + 4]);
        }
        #pragma unroll
        for (int ni = 0; ni < 4; ni++) {
            int n = wn * 32 + ni * 8 + grp;
            bf[ni][0] = __float_as_uint(Ks[n][kk8 + qd    ]);
            bf[ni][1] = __float_as_uint(Ks[n][kk8 + qd + 4]);
        }
        #pragma unroll
        for (int mi = 0; mi < 4; mi++)
            #pragma unroll
            for (int ni = 0; ni < 4; ni++)
                mma_tf32(acc[mi][ni], a[mi][0], a[mi][1], a[mi][2], a[mi][3],
                         bf[ni][0], bf[ni][1]);
    }
    __syncthreads();

    const float alpha = 0.125f;
    #pragma unroll
    for (int mi = 0; mi < 4; mi++)
        #pragma unroll
        for (int ni = 0; ni < 4; ni++)
            #pragma unroll
            for (int j = 0; j < 4; j++)
                acc[mi][ni][j] *= alpha;

    float msel[4][2];
    #pragma unroll
    for (int mi = 0; mi < 4; mi++) {
        float mA = -1e30f, mB = -1e30f;
        #pragma unroll
        for (int ni = 0; ni < 4; ni++) {
            mA = fmaxf(mA, fmaxf(acc[mi][ni][0], acc[mi][ni][1]));
            mB = fmaxf(mB, fmaxf(acc[mi][ni][2], acc[mi][ni][3]));
        }
        mA = fmaxf(mA, __shfl_xor_sync(0xffffffffu, mA, 1));
        mA = fmaxf(mA, __shfl_xor_sync(0xffffffffu, mA, 2));
        mB = fmaxf(mB, __shfl_xor_sync(0xffffffffu, mB, 1));
        mB = fmaxf(mB, __shfl_xor_sync(0xffffffffu, mB, 2));
        int rA = wm * 64 + mi * 16 + grp;
        if (qd == 0) { rstat[rA][wn] = mA; rstat[rA + 8][wn] = mB; }
    }
    __syncthreads();
    #pragma unroll
    for (int mi = 0; mi < 4; mi++) {
        int rA = wm * 64 + mi * 16 + grp;
        msel[mi][0] = fmaxf(fmaxf(rstat[rA][0],     rstat[rA][1]),
                            fmaxf(rstat[rA][2],     rstat[rA][3]));
        msel[mi][1] = fmaxf(fmaxf(rstat[rA + 8][0], rstat[rA + 8][1]),
                            fmaxf(rstat[rA + 8][2], rstat[rA + 8][3]));
    }
    __syncthreads();

    float ssel[4][2];
    #pragma unroll
    for (int mi = 0; mi < 4; mi++) {
        float sA = 0.f, sB = 0.f;
        #pragma unroll
        for (int ni = 0; ni < 4; ni++) {
            acc[mi][ni][0] = __expf(acc[mi][ni][0] - msel[mi][0]);
            acc[mi][ni][1] = __expf(acc[mi][ni][1] - msel[mi][0]);
            acc[mi][ni][2] = __expf(acc[mi][ni][2] - msel[mi][1]);
            acc[mi][ni][3] = __expf(acc[mi][ni][3] - msel[mi][1]);
            sA += acc[mi][ni][0] + acc[mi][ni][1];
            sB += acc[mi][ni][2] + acc[mi][ni][3];
        }
        sA += __shfl_xor_sync(0xffffffffu, sA, 1);
        sA += __shfl_xor_sync(0xffffffffu, sA, 2);
        sB += __shfl_xor_sync(0xffffffffu, sB, 1);
        sB += __shfl_xor_sync(0xffffffffu, sB, 2);
        int rA = wm * 64 + mi * 16 + grp;
        if (qd == 0) { rstat[rA][wn] = sA; rstat[rA + 8][wn] = sB; }
    }
    __syncthreads();
    #pragma unroll
    for (int mi = 0; mi < 4; mi++) {
        int rA = wm * 64 + mi * 16 + grp;
        ssel[mi][0] = (rstat[rA][0]     + rstat[rA][1])
                    + (rstat[rA][2]     + rstat[rA][3]);
        ssel[mi][1] = (rstat[rA + 8][0] + rstat[rA + 8][1])
                    + (rstat[rA + 8][2] + rstat[rA + 8][3]);
    }

    float* ob = score + (size_t)bh * SEQ * SEQ;
    int row0 = blockIdx.y * 128 + wm * 64;
    int col0 = blockIdx.x * 128 + wn * 32;
    #pragma unroll
    for (int mi = 0; mi < 4; mi++) {
        #pragma unroll
        for (int ni = 0; ni < 4; ni++) {
            int r  = row0 + mi * 16 + grp;
            int cc = col0 + ni * 8 + qd * 2;
            *(float2*)(ob + (size_t)r * SEQ + cc) =
                make_float2(acc[mi][ni][0], acc[mi][ni][1]);
            *(float2*)(ob + (size_t)(r + 8) * SEQ + cc) =
                make_float2(acc[mi][ni][2], acc[mi][ni][3]);
        }
    }

    if (wn == 0 && qd == 0) {
        #pragma unroll
        for (int mi = 0; mi < 4; mi++) {
            #pragma unroll
            for (int half = 0; half < 2; half++) {
                int rowg = blockIdx.y * 128 + wm * 64 + mi * 16 + half * 8 + grp;
                size_t idx = ((size_t)(bh << 11) + rowg) * NCT + blockIdx.x;
                g_smax[idx] = msel[mi][half];
                g_ssum[idx] = ssel[mi][half];
            }
        }
    }
}

// ---------------------------------------------------------------------------
// PV v3: inline combine (per-block factor table) + 256 threads, CHK=32.
// ---------------------------------------------------------------------------
#define CHK2 32
#define PVP 36
#define PV_SMEM ((128 * PVP + 2 * CHK2 * 72) * 4)   // 36864 bytes dynamic

__global__ __launch_bounds__(256, 2) void attn_pv3(float* __restrict__ score)
{
    extern __shared__ float smraw[];
    unsigned (*Ps)[PVP]       = (unsigned (*)[PVP])smraw;
    unsigned (*Vs)[CHK2][72]  = (unsigned (*)[CHK2][72])(smraw + 128 * PVP);
    __shared__ float fb_s[128][NCT];

    int tid = threadIdx.x;
    int warp = tid >> 5, lane = tid & 31;
    int wm = warp >> 2, wn = warp & 3;     // 2 x 4
    int grp = lane >> 2, qd = lane & 3;
    int bh = blockIdx.y, b = bh >> 4, h = bh & 15;
    int row0 = blockIdx.x * 128;

    float* pb = score + (size_t)bh * SEQ * SEQ + (size_t)row0 * SEQ;
    const float* vb = g_v + (size_t)b * SEQ * DIM + h * DK;

    // inline combine: one thread per row computes the 16 tile factors
    if (tid < 128) {
        size_t row_g = (size_t)(bh << 11) + row0 + tid;
        const float* mx = g_smax + row_g * NCT;
        const float* sv = g_ssum + row_g * NCT;
        float mv[NCT];
        float m = -1e30f;
        #pragma unroll
        for (int i = 0; i < NCT; i++) { mv[i] = mx[i]; m = fmaxf(m, mv[i]); }
        float s = 0.f;
        float ev[NCT];
        #pragma unroll
        for (int i = 0; i < NCT; i++) { ev[i] = __expf(mv[i] - m); s += sv[i] * ev[i]; }
        float inv = 1.0f / s;
        #pragma unroll
        for (int i = 0; i < NCT; i++) fb_s[tid][i] = ev[i] * inv;
    }
    __syncthreads();

    float acc[4][2][4] = {};
    float4 pe[4]; float pf[4]; float4 pvv[2];

    // prologue: chunk 0
    #pragma unroll
    for (int i = 0; i < 4; i++) {
        int id = tid + i * 256;
        int r  = id >> 3;
        int c4 = (id & 7) << 2;
        pe[i] = *(const float4*)(pb + (size_t)r * SEQ + c4);
        pf[i] = fb_s[r][0];
    }
    #pragma unroll
    for (int i = 0; i < 2; i++) {
        int id = tid + i * 256;
        int r  = id >> 4;
        int c4 = (id & 15) << 2;
        pvv[i] = *(const float4*)(vb + (size_t)r * DIM + c4);
    }
    #pragma unroll
    for (int i = 0; i < 4; i++) {
        int id = tid + i * 256;
        int r  = id >> 3;
        int c4 = (id & 7) << 2;
        float4 p = make_float4(pe[i].x * pf[i], pe[i].y * pf[i],
                               pe[i].z * pf[i], pe[i].w * pf[i]);
        *(float4*)(pb + (size_t)r * SEQ + c4) = p;
        *(uint4*)&Ps[r][c4] = make_uint4(f2tf(p.x), f2tf(p.y), f2tf(p.z), f2tf(p.w));
    }
    #pragma unroll
    for (int i = 0; i < 2; i++) {
        int id = tid + i * 256;
        int r  = id >> 4;
        int c4 = (id & 15) << 2;
        *(uint4*)&Vs[0][r][c4] = make_uint4(
            __float_as_uint(pvv[i].x), __float_as_uint(pvv[i].y),
            __float_as_uint(pvv[i].z), __float_as_uint(pvv[i].w));
    }
    __syncthreads();

    const int NTCH = SEQ / CHK2;   // 64
    for (int t = 0; t < NTCH; t++) {
        int cur = t & 1;
        if (t + 1 < NTCH) {
            int ct = (t + 1) >> 2;
            #pragma unroll
            for (int i = 0; i < 4; i++) {
                int id = tid + i * 256;
                int r  = id >> 3;
                int c4 = (id & 7) << 2;
                pe[i] = *(const float4*)(pb + (size_t)r * SEQ + (t + 1) * CHK2 + c4);
                pf[i] = fb_s[r][ct];
            }
            #pragma unroll
            for (int i = 0; i < 2; i++) {
                int id = tid + i * 256;
                int r  = id >> 4;
                int c4 = (id & 15) << 2;
                pvv[i] = *(const float4*)(vb + (size_t)((t + 1) * CHK2 + r) * DIM + c4);
            }
        }

        // PV MMA: acc += P[128xCHK2] @ V[CHK2x64]; warp tile 64x16
        #pragma unroll
        for (int kk = 0; kk < CHK2; kk += 8) {
            unsigned a[4][4], bf[2][2];
            #pragma unroll
            for (int mi = 0; mi < 4; mi++) {
                int m = wm * 64 + mi * 16;
                a[mi][0] = Ps[m + grp    ][kk + qd    ];
                a[mi][1] = Ps[m + grp + 8][kk + qd    ];
                a[mi][2] = Ps[m + grp    ][kk + qd + 4];
                a[mi][3] = Ps[m + grp + 8][kk + qd + 4];
            }
            #pragma unroll
            for (int ni = 0; ni < 2; ni++) {
                int n = wn * 16 + ni * 8 + grp;
                bf[ni][0] = Vs[cur][kk + qd    ][n];
                bf[ni][1] = Vs[cur][kk + qd + 4][n];
            }
            #pragma unroll
            for (int mi = 0; mi < 4; mi++)
                #pragma unroll
                for (int ni = 0; ni < 2; ni++)
                    mma_tf32(acc[mi][ni], a[mi][0], a[mi][1], a[mi][2], a[mi][3],
                             bf[ni][0], bf[ni][1]);
        }
        __syncthreads();   // MMA reads of Ps/Vs[cur] done

        if (t + 1 < NTCH) {
            int nxt = cur ^ 1;
            #pragma unroll
            for (int i = 0; i < 4; i++) {
                int id = tid + i * 256;
                int r  = id >> 3;
                int c4 = (id & 7) << 2;
                float4 p = make_float4(pe[i].x * pf[i], pe[i].y * pf[i],
                                       pe[i].z * pf[i], pe[i].w * pf[i]);
                *(float4*)(pb + (size_t)r * SEQ + (t + 1) * CHK2 + c4) = p;
                *(uint4*)&Ps[r][c4] = make_uint4(f2tf(p.x), f2tf(p.y), f2tf(p.z), f2tf(p.w));
            }
            #pragma unroll
            for (int i = 0; i < 2; i++) {
                int id = tid + i * 256;
                int r  = id >> 4;
                int c4 = (id & 15) << 2;
                *(uint4*)&Vs[nxt][r][c4] = make_uint4(
                    __float_as_uint(pvv[i].x), __float_as_uint(pvv[i].y),
                    __float_as_uint(pvv[i].z), __float_as_uint(pvv[i].w));
            }
            __syncthreads();
        }
    }

    // store blended pre-rounded to tf32 bits for the cvt-free out-proj GEMM
    float* ob = g_bl + (size_t)b * SEQ * DIM;
    int r0 = row0 + wm * 64;
    int c0 = h * DK + wn * 16;
    #pragma unroll
    for (int mi = 0; mi < 4; mi++) {
        #pragma unroll
        for (int ni = 0; ni < 2; ni++) {
            int r  = r0 + mi * 16 + grp;
            int cc = c0 + ni * 8 + qd * 2;
            float2 o0 = make_float2(__uint_as_float(f2tf(acc[mi][ni][0])),
                                    __uint_as_float(f2tf(acc[mi][ni][1])));
            float2 o1 = make_float2(__uint_as_float(f2tf(acc[mi][ni][2])),
                                    __uint_as_float(f2tf(acc[mi][ni][3])));
            *(float2*)(ob + (size_t)r * DIM + cc)       = o0;
            *(float2*)(ob + (size_t)(r + 8) * DIM + cc) = o1;
        }
    }
}

// ---------------------------------------------------------------------------
extern "C" void kernel_launch(void* const* d_in, const int* in_sizes, int n_in,
                              void* d_out, int out_size)
{
    const float* query = (const float*)d_in[0];
    const float* key   = (const float*)d_in[1];
    const float* value = (const float*)d_in[2];
    const float* Wq    = (const float*)d_in[3];
    const float* bq    = (const float*)d_in[4];
    const float* Wk    = (const float*)d_in[5];
    const float* bk    = (const float*)d_in[6];
    const float* Wv    = (const float*)d_in[7];
    const float* bv    = (const float*)d_in[8];
    const float* Wo    = (const float*)d_in[9];
    const float* bo    = (const float*)d_in[10];

    float* out   = (float*)d_out;                          // [B,S,D]
    float* score = out + (size_t)BSZ * SEQ * DIM;          // [B,H,S,S]

    float *pq, *pk, *pv, *pbl, *prq, *prk, *prv, *pw;
    cudaGetSymbolAddress((void**)&pq,  g_q);
    cudaGetSymbolAddress((void**)&pk,  g_k);
    cudaGetSymbolAddress((void**)&pv,  g_v);
    cudaGetSymbolAddress((void**)&pbl, g_bl);
    cudaGetSymbolAddress((void**)&prq, g_rq);
    cudaGetSymbolAddress((void**)&prk, g_rk);
    cudaGetSymbolAddress((void**)&prv, g_rv);
    cudaGetSymbolAddress((void**)&pw,  g_w);

    cudaFuncSetAttribute(gemm_qk,
        cudaFuncAttributeMaxDynamicSharedMemorySize, GEMM_SMEM);
    cudaFuncSetAttribute(gemm_cpa,
        cudaFuncAttributeMaxDynamicSharedMemorySize, GEMM_SMEM);
    cudaFuncSetAttribute(attn_scores_v3,
        cudaFuncAttributeMaxDynamicSharedMemorySize, SC_SMEM);
    cudaFuncSetAttribute(attn_pv3,
        cudaFuncAttributeMaxDynamicSharedMemorySize, PV_SMEM);

    // Was the launch stream capturing? (determines whether we may destroy
    // the fork stream at the end; querying capture status is capture-legal)
    cudaStreamCaptureStatus cs = cudaStreamCaptureStatusNone;
    cudaStreamIsCapturing(cudaStreamLegacy, &cs);

    cudaStream_t s2;
    cudaStreamCreate(&s2);
    cudaEvent_t evA, evB;
    cudaEventCreateWithFlags(&evA, cudaEventDisableTiming);
    cudaEventCreateWithFlags(&evB, cudaEventDisableTiming);

    // pre-round inputs + weights to tf32 bits (default stream)
    round3<<<dim3(MTOT * DIM / 4 / 256, 3), 256>>>(query, key, value, prq, prk, prv);
    round4<<<dim3(DIM * DIM / 4 / 256, 4), 256>>>(Wq, Wk, Wv, Wo, pw);

    // fork: V projection runs concurrently with QK projections + scores
    cudaEventRecord(evA, 0);
    cudaStreamWaitEvent(s2, evA, 0);
    gemm_cpa<<<dim3(DIM / 128, MTOT / 128), 256, GEMM_SMEM, s2>>>(
        prv, pw + 2 * (size_t)DIM * DIM, bv, pv, MTOT, DIM, DIM, 1);
    cudaEventRecord(evB, s2);

    // main path
    gemm_qk<<<dim3(DIM / 128, MTOT / 128, 2), 256, GEMM_SMEM>>>(
        prq, prk, pw, bq, bk, pq, pk);
    attn_scores_v3<<<dim3(SEQ / 128, SEQ / 128, BH), 256, SC_SMEM>>>(score);

    // join: PV needs V
    cudaStreamWaitEvent(0, evB, 0);
    attn_pv3<<<dim3(SEQ / 128, BH), 256, PV_SMEM>>>(score);

    gemm_cpa<<<dim3(DIM / 128, MTOT / 128), 256, GEMM_SMEM>>>(
        pbl, pw + 3 * (size_t)DIM * DIM, bo, out, MTOT, DIM, DIM, 0);

    if (cs == cudaStreamCaptureStatusNone) {
        // not capturing: safe to clean up host-side resources now
        cudaStreamDestroy(s2);
        cudaEventDestroy(evA);
        cudaEventDestroy(evB);
    }
    // (capturing: handles are intentionally left alive; the graph owns the
    //  dependency structure and the few host objects are a one-time cost)
}